// round 13
// baseline (speedup 1.0000x reference)
#include <cuda_runtime.h>

#define FULLMASK 0xffffffffu
#define IH 256
#define IW 192

// Gaussian taps for kernel_size=11, sigma=10/6, normalized. Indexed by |d|.
// Used as compile-time float literals -> FFMA immediate forms (rt_SMSP=1).
static __device__ __forceinline__ float wt(int k) {
    const float t[6] = {0.23955940f, 0.20009682f, 0.11660614f,
                        0.04740849f, 0.01344761f, 0.00266126f};
    return t[k];
}

// One step of the fused blur/argmax pipeline (3 cols/lane, scalar FFMA-imm).
//  U      : static slot phase (i mod 11)
//  GUARD  : head/tail mode — runtime row bounds checks (warp-uniform)
//  EMIT   : emit completed output row (slot U) into the running argmax
// cur holds row r (3 own cols); consumes it, loads row r+1 into cur.
// lload/rload: warp-uniform flags — interior col boundary needs real halo
// loads on lane 0 (left, cols 91..95) / lane 31 (right, cols 96..100).
template<int U, bool GUARD, bool EMIT>
static __device__ __forceinline__ void step(
    const float* __restrict__ rp,    // main mode: &row(r+1 at U=0)[c0]
    const float* __restrict__ epb,   // main mode: &row(r at U=0)[0] (uniform)
    const float* __restrict__ ip,    // image base (GUARD-mode addressing)
    int r, int c0, int lane, bool lload, bool rload,
    float (&cur)[3], float (&acc)[11][3],
    float& bestv, int& bestlin, int ebl)
{
    // ---- load row r+1 (own 3 cols) ----
    float n0 = 0.f, n1 = 0.f, n2 = 0.f;
    bool rowok = true, loadok = true;
    if (GUARD) {
        loadok = ((unsigned)(r + 1) < (unsigned)IH);
        rowok  = ((unsigned)r       < (unsigned)IH);
    }
    if (loadok) {
        const float* p = GUARD ? (ip + (r + 1) * IW + c0) : (rp + U * IW);
        n0 = p[0]; n1 = p[1]; n2 = p[2];
    }

    if (rowok) {
        // ---- interior-boundary halo loads (current row r) ----
        float ed0 = 0.f, ed1 = 0.f, ed2 = 0.f, ed3 = 0.f, ed4 = 0.f;
        {
            const float* eb = GUARD ? (ip + r * IW) : (epb + U * IW);
            if (lload && lane == 0) {           // cols 91..95
                ed0 = eb[91]; ed1 = eb[92]; ed2 = eb[93];
                ed3 = eb[94]; ed4 = eb[95];
            }
            if (rload && lane == 31) {          // cols 96..100
                ed0 = eb[96]; ed1 = eb[97]; ed2 = eb[98];
                ed3 = eb[99]; ed4 = eb[100];
            }
        }

        // ---- halo shuffles: e[k] = col c0-5+k, k=0..12 ----
        float e0  = __shfl_up_sync(FULLMASK, cur[1], 2);
        float e1  = __shfl_up_sync(FULLMASK, cur[2], 2);
        float e2  = __shfl_up_sync(FULLMASK, cur[0], 1);
        float e3  = __shfl_up_sync(FULLMASK, cur[1], 1);
        float e4  = __shfl_up_sync(FULLMASK, cur[2], 1);
        const float e5 = cur[0], e6 = cur[1], e7 = cur[2];
        float e8  = __shfl_down_sync(FULLMASK, cur[0], 1);
        float e9  = __shfl_down_sync(FULLMASK, cur[1], 1);
        float e10 = __shfl_down_sync(FULLMASK, cur[2], 1);
        float e11 = __shfl_down_sync(FULLMASK, cur[0], 2);
        float e12 = __shfl_down_sync(FULLMASK, cur[1], 2);

        // boundary patch values for lanes 1 / 30 (from lane 0 / 31 loads)
        const float s94 = __shfl_sync(FULLMASK, ed3, 0);
        const float s95 = __shfl_sync(FULLMASK, ed4, 0);
        const float t96 = __shfl_sync(FULLMASK, ed0, 31);
        const float t97 = __shfl_sync(FULLMASK, ed1, 31);

        if (lane == 0)  { e0 = ed0; e1 = ed1; e2 = ed2; e3 = ed3; e4 = ed4; }
        if (lane == 1)  { e0 = s94; e1 = s95; }
        if (lane == 30) { e11 = t96; e12 = t97; }
        if (lane == 31) { e8 = ed0; e9 = ed1; e10 = ed2; e11 = ed3; e12 = ed4; }

        // ---- horizontal blur (scalar, even/odd split chains, imm taps) ----
        float h0, h1, h2;
        {
            float sa = e0 * wt(5);
            sa = fmaf(e2,  wt(3), sa);
            sa = fmaf(e4,  wt(1), sa);
            sa = fmaf(e6,  wt(1), sa);
            sa = fmaf(e8,  wt(3), sa);
            sa = fmaf(e10, wt(5), sa);
            float sb = e1 * wt(4);
            sb = fmaf(e3, wt(2), sb);
            sb = fmaf(e5, wt(0), sb);
            sb = fmaf(e7, wt(2), sb);
            sb = fmaf(e9, wt(4), sb);
            h0 = sa + sb;
        }
        {
            float sa = e1 * wt(5);
            sa = fmaf(e3,  wt(3), sa);
            sa = fmaf(e5,  wt(1), sa);
            sa = fmaf(e7,  wt(1), sa);
            sa = fmaf(e9,  wt(3), sa);
            sa = fmaf(e11, wt(5), sa);
            float sb = e2 * wt(4);
            sb = fmaf(e4,  wt(2), sb);
            sb = fmaf(e6,  wt(0), sb);
            sb = fmaf(e8,  wt(2), sb);
            sb = fmaf(e10, wt(4), sb);
            h1 = sa + sb;
        }
        {
            float sa = e2 * wt(5);
            sa = fmaf(e4,  wt(3), sa);
            sa = fmaf(e6,  wt(1), sa);
            sa = fmaf(e8,  wt(1), sa);
            sa = fmaf(e10, wt(3), sa);
            sa = fmaf(e12, wt(5), sa);
            float sb = e3 * wt(4);
            sb = fmaf(e5,  wt(2), sb);
            sb = fmaf(e7,  wt(0), sb);
            sb = fmaf(e9,  wt(2), sb);
            sb = fmaf(e11, wt(4), sb);
            h2 = sa + sb;
        }

        // ---- vertical taps: k=0..9 accumulate, k=10 overwrites recycled slot
#pragma unroll
        for (int k = 0; k < 10; ++k) {
            const float wv = wt(k <= 5 ? 5 - k : k - 5);
            const int s = (U + k) % 11;
            acc[s][0] = fmaf(h0, wv, acc[s][0]);
            acc[s][1] = fmaf(h1, wv, acc[s][1]);
            acc[s][2] = fmaf(h2, wv, acc[s][2]);
        }
        {
            const int s = (U + 10) % 11;
            acc[s][0] = h0 * wt(5);
            acc[s][1] = h1 * wt(5);
            acc[s][2] = h2 * wt(5);
        }
    } else {
        const int s = (U + 10) % 11;
        acc[s][0] = 0.f; acc[s][1] = 0.f; acc[s][2] = 0.f;
    }

    if (EMIT) {
        const float a0 = acc[U][0], a1 = acc[U][1], a2 = acc[U][2];
        const float rowmax = fmaxf(fmaxf(a0, a1), a2);
        if (rowmax > bestv) {        // rare
            bestv = rowmax;
            int c = 2;
            if (a1 == rowmax) c = 1;
            if (a0 == rowmax) c = 0;
            bestlin = ebl + U * IW + c;
        }
    }

    cur[0] = n0; cur[1] = n1; cur[2] = n2;
}

// One CTA (128 threads = 4 warps) per (b,k) image.
// warp = (rowhalf<<1)|colhalf : rows [rowhalf*128, +128) x cols [colhalf*96, +96).
// Lane owns 3 cols (c0 = cb + 3*lane). Head 11 guarded + main 11x11 + tail 6.
__global__ __launch_bounds__(128, 7)
void dark_decode_kernel(const float* __restrict__ hm,
                        float* __restrict__ out, int n_img)
{
    const int img  = blockIdx.x;
    const int warp = threadIdx.x >> 5;
    const int lane = threadIdx.x & 31;
    const float* __restrict__ ip = hm + (long long)img * (IH * IW);

    const int rowhalf = warp >> 1;
    const int colhalf = warp & 1;
    const int base = rowhalf * 128;       // output rows [base, base+128)
    const int cb   = colhalf * 96;        // output cols [cb, cb+96)
    const int c0   = cb + 3 * lane;
    const bool lload = (colhalf == 1);    // left halo is interior -> load
    const bool rload = (colhalf == 0);    // right halo is interior -> load

    float acc[11][3];   // no init needed: every slot overwritten before emit

    float cur[3];
    {   // row base-5 (rowhalf 0: OOB -> zeros)
        const int r0 = base - 5;
        if (r0 >= 0) {
            const float* p = ip + r0 * IW + c0;
            cur[0] = p[0]; cur[1] = p[1]; cur[2] = p[2];
        } else {
            cur[0] = 0.f; cur[1] = 0.f; cur[2] = 0.f;
        }
    }

    float bestv   = -3.4e38f;
    int   bestlin = 0;

    // ---- head: i = 0..10 (r = base-5+i), guarded; emit only at i=10 ----
    {
        const int eblh = (base - 10) * IW + c0;
#define HSTEP(U, EM) step<U, true, EM>(ip, ip, ip, base - 5 + (U), c0, lane, \
                        lload, rload, cur, acc, bestv, bestlin, eblh)
        HSTEP(0, false); HSTEP(1, false); HSTEP(2, false); HSTEP(3, false);
        HSTEP(4, false); HSTEP(5, false); HSTEP(6, false); HSTEP(7, false);
        HSTEP(8, false); HSTEP(9, false); HSTEP(10, true);
#undef HSTEP
    }

    // ---- main: i = 11..131, 11 blocks x 11 steps, branch-free ----
    // step i: consumes row base-5+i, loads row base-4+i (max base+127, in range)
    {
        const float* rp  = ip + (base + 7) * IW + c0;   // row r+1 at ib=0,U=0
        const float* epb = ip + (base + 6) * IW;        // row r   at ib=0,U=0
        int ebl = (base + 1) * IW + c0;                 // ro at ib=0,U=0
#define MSTEP(U) step<U, false, true>(rp, epb, ip, 0, c0, lane, lload, rload, \
                        cur, acc, bestv, bestlin, ebl)
        for (int ib = 0; ib < 11; ++ib) {
            MSTEP(0); MSTEP(1); MSTEP(2); MSTEP(3); MSTEP(4); MSTEP(5);
            MSTEP(6); MSTEP(7); MSTEP(8); MSTEP(9); MSTEP(10);
            rp  += 11 * IW;
            epb += 11 * IW;
            ebl += 11 * IW;
        }
#undef MSTEP
    }

    // ---- tail: i = 132..137 (U = 0..5, r = base+127+U), guarded, emit ----
    {
        const int eblt = (base + 122) * IW + c0;
#define TSTEP(U) step<U, true, true>(ip, ip, ip, base + 127 + (U), c0, lane, \
                        lload, rload, cur, acc, bestv, bestlin, eblt)
        TSTEP(0); TSTEP(1); TSTEP(2); TSTEP(3); TSTEP(4); TSTEP(5);
#undef TSTEP
    }

    // intra-warp argmax reduce (larger value wins; tie -> smaller linear index)
#pragma unroll
    for (int off = 16; off >= 1; off >>= 1) {
        const float ov = __shfl_xor_sync(FULLMASK, bestv, off);
        const int   oi = __shfl_xor_sync(FULLMASK, bestlin, off);
        if (ov > bestv || (ov == bestv && oi < bestlin)) { bestv = ov; bestlin = oi; }
    }

    __shared__ float s_v[4];
    __shared__ int   s_i[4];
    if (lane == 0) { s_v[warp] = bestv; s_i[warp] = bestlin; }
    __syncthreads();
    if (warp != 0) return;

    float fv = s_v[0]; int fl = s_i[0];
#pragma unroll
    for (int w = 1; w < 4; ++w) {
        const float vw = s_v[w]; const int iw = s_i[w];
        if (vw > fv || (vw == fv && iw < fl)) { fv = vw; fl = iw; }
    }
    const int py = fl / IW;
    const int px = fl - py * IW;

    float offx = 0.f, offy = 0.f;
    const bool bok = (px >= 1) && (px < IW - 1) && (py >= 1) && (py < IH - 1);
    if (bok) {
        // 39 hblur values: flat j in [0,39), rr = py-6 + j/3, cc = px-1 + j%3
        float h0 = 0.f, h1 = 0.f;
        {
            int j = lane;
            int rr = py - 6 + j / 3;
            int cc = px - 1 + (j - (j / 3) * 3);
            if (rr >= 0 && rr < IH) {
                const float* rp2 = ip + rr * IW;
                float s = 0.f;
#pragma unroll
                for (int d = -5; d <= 5; ++d) {
                    const int c = cc + d;
                    float v = 0.f;
                    if ((unsigned)c < (unsigned)IW) v = rp2[c];
                    s += v * wt(d < 0 ? -d : d);
                }
                h0 = s;
            }
            j = lane + 32;
            if (j < 39) {
                rr = py - 6 + j / 3;
                cc = px - 1 + (j - (j / 3) * 3);
                if (rr >= 0 && rr < IH) {
                    const float* rp2 = ip + rr * IW;
                    float s = 0.f;
#pragma unroll
                    for (int d = -5; d <= 5; ++d) {
                        const int c = cc + d;
                        float v = 0.f;
                        if ((unsigned)c < (unsigned)IW) v = rp2[c];
                        s += v * wt(d < 0 ? -d : d);
                    }
                    h1 = s;
                }
            }
        }
        // lanes 0..8: vertical blur -> patch entry p(a,b), a=lane/3, b=lane%3
        const int a = lane / 3;
        const int b = lane - a * 3;
        float p = 0.f;
#pragma unroll
        for (int t = 0; t < 11; ++t) {
            const int j = (a + t) * 3 + b;
            const float va = __shfl_sync(FULLMASK, h0, j & 31);
            const float vb = __shfl_sync(FULLMASK, h1, j & 31);
            const float hv = (j < 32) ? va : vb;
            p += hv * wt(t <= 5 ? 5 - t : t - 5);
        }
        const float p00 = __shfl_sync(FULLMASK, p, 0);
        const float p01 = __shfl_sync(FULLMASK, p, 1);
        const float p02 = __shfl_sync(FULLMASK, p, 2);
        const float p10 = __shfl_sync(FULLMASK, p, 3);
        const float p11 = __shfl_sync(FULLMASK, p, 4);
        const float p12 = __shfl_sync(FULLMASK, p, 5);
        const float p20 = __shfl_sync(FULLMASK, p, 6);
        const float p21 = __shfl_sync(FULLMASK, p, 7);
        const float p22 = __shfl_sync(FULLMASK, p, 8);

        const float dx  = (p12 - p10) * 0.5f;
        const float dy  = (p21 - p01) * 0.5f;
        const float dxx = p12 - 2.f * p11 + p10;
        const float dyy = p21 - 2.f * p11 + p01;
        const float dxy = (p22 - p20 - p02 + p00) * 0.25f;
        const float det = dxx * dyy - dxy * dxy;
        if (fabsf(det) >= 1e-6f && dxx < 0.f) {
            const float ox = -(dyy * dx - dxy * dy) / det;
            const float oy = -(dxx * dy - dxy * dx) / det;
            offx = fminf(fmaxf(ox, -0.5f), 0.5f);
            offy = fminf(fmaxf(oy, -0.5f), 0.5f);
        }
    }

    if (lane == 0) {
        const float xo = fminf(fmaxf((float)px + offx, 0.f), (float)(IW - 1));
        const float yo = fminf(fmaxf((float)py + offy, 0.f), (float)(IH - 1));
        out[2 * img + 0] = xo;                       // coords[...,0] = x
        out[2 * img + 1] = yo;                       // coords[...,1] = y
        out[(long long)2 * n_img + img] = fv;        // max_vals
    }
}

extern "C" void kernel_launch(void* const* d_in, const int* in_sizes, int n_in,
                              void* d_out, int out_size)
{
    const float* hm = (const float*)d_in[0];
    // d_in[1] is kernel_size (always 11 in this problem; taps are baked in)
    const int n_img = in_sizes[0] / (IH * IW);
    dark_decode_kernel<<<n_img, 128>>>(hm, (float*)d_out, n_img);
}

// round 14
// speedup vs baseline: 1.7936x; 1.7936x over previous
#include <cuda_runtime.h>

#define FULLMASK 0xffffffffu
#define IH 256
#define IW 192

typedef unsigned long long u64;

// Gaussian taps for kernel_size=11, sigma=10/6, normalized. Indexed by |d|.
static __device__ __forceinline__ float wt(int k) {
    const float t[6] = {0.23955940f, 0.20009682f, 0.11660614f,
                        0.04740849f, 0.01344761f, 0.00266126f};
    return t[k];
}

static __device__ __forceinline__ u64 pk(float lo, float hi) {
    u64 r; asm("mov.b64 %0, {%1, %2};" : "=l"(r) : "f"(lo), "f"(hi)); return r;
}
static __device__ __forceinline__ void upk(u64 v, float& lo, float& hi) {
    asm("mov.b64 {%0, %1}, %2;" : "=f"(lo), "=f"(hi) : "l"(v));
}
static __device__ __forceinline__ float f2lo(u64 v) { float a, b; upk(v, a, b); return a; }
static __device__ __forceinline__ float f2hi(u64 v) { float a, b; upk(v, a, b); return b; }
static __device__ __forceinline__ u64 f2mul(u64 a, u64 b) {
    u64 d; asm("mul.rn.f32x2 %0, %1, %2;" : "=l"(d) : "l"(a), "l"(b)); return d;
}
static __device__ __forceinline__ u64 f2fma(u64 a, u64 b, u64 c) {
    u64 d; asm("fma.rn.f32x2 %0, %1, %2, %3;" : "=l"(d) : "l"(a), "l"(b), "l"(c)); return d;
}
static __device__ __forceinline__ u64 f2add(u64 a, u64 b) {
    u64 d; asm("add.rn.f32x2 %0, %1, %2;" : "=l"(d) : "l"(a), "l"(b)); return d;
}

// One step of the fused blur/argmax pipeline (prefetch distance 1).
// Pair-native halos: own row kept as 3 aligned u64 pairs; neighbor pairs
// shuffled as u64 (aligned, no repack); only 8 cross pairs need rebuilds.
//  U      : static slot phase (i mod 11)
//  GUARD  : head/tail mode — runtime row/load bounds checks (warp-uniform)
//  EMIT   : emit completed output row (slot U) into the running argmax
// cur holds row r (pairs); consumes it, loads row r+1 into cur.
template<int U, bool GUARD, bool EMIT>
static __device__ __forceinline__ void step(
    const float* __restrict__ rp,   // main-mode load base: row of U=0 load
    const float* __restrict__ ip,   // image base (GUARD-mode addressing)
    int r, int col0,
    u64 (&cur)[3], u64 (&acc)[11][3], const u64 (&w2)[6],
    bool l0, bool l31, float& bestv, int& bestlin, int ebl)
{
    // ---- load row r+1 (3 aligned pairs) ----
    u64 nc0 = 0ull, nc1 = 0ull, nc2 = 0ull;
    bool loadok = true, rowok = true;
    if (GUARD) {
        loadok = ((unsigned)(r + 1) < (unsigned)IH);
        rowok  = ((unsigned)r       < (unsigned)IH);
    }
    if (loadok) {
        const u64* p = reinterpret_cast<const u64*>(
            GUARD ? (ip + (r + 1) * IW + col0) : (rp + U * IW));
        nc0 = p[0]; nc1 = p[1]; nc2 = p[2];
    }

    if (rowok) {
        // ---- pair halos via u64 shuffles (aligned pairs arrive pre-packed)
        u64 P1  = __shfl_up_sync(FULLMASK, cur[1], 1);    // (c0-4, c0-3)
        u64 P3  = __shfl_up_sync(FULLMASK, cur[2], 1);    // (c0-2, c0-1)
        u64 P11 = __shfl_down_sync(FULLMASK, cur[0], 1);  // (c0+6, c0+7)
        u64 P13 = __shfl_down_sync(FULLMASK, cur[1], 1);  // (c0+8, c0+9)
        float e0  = __shfl_up_sync(FULLMASK, f2hi(cur[0]), 1);   // c0-5
        float e15 = __shfl_down_sync(FULLMASK, f2lo(cur[2]), 1); // c0+10
        if (l0)  { P1 = 0ull; P3 = 0ull; e0 = 0.f; }
        if (l31) { P11 = 0ull; P13 = 0ull; e15 = 0.f; }

        // ---- full pair set P[0..14]; 7 aligned (free), 8 crosses (2 MOV ea)
        u64 P[15];
        P[0]  = pk(e0, f2lo(P1));
        P[1]  = P1;
        P[2]  = pk(f2hi(P1), f2lo(P3));
        P[3]  = P3;
        P[4]  = pk(f2hi(P3), f2lo(cur[0]));
        P[5]  = cur[0];
        P[6]  = pk(f2hi(cur[0]), f2lo(cur[1]));
        P[7]  = cur[1];
        P[8]  = pk(f2hi(cur[1]), f2lo(cur[2]));
        P[9]  = cur[2];
        P[10] = pk(f2hi(cur[2]), f2lo(P11));
        P[11] = P11;
        P[12] = pk(f2hi(P11), f2lo(P13));
        P[13] = P13;
        P[14] = pk(f2hi(P13), e15);

        // ---- horizontal blur (packed, even/odd split chains) ----
        u64 h2[3];
#pragma unroll
        for (int j = 0; j < 3; ++j) {
            u64 sa = f2mul(P[2*j + 0], w2[5]);
            sa = f2fma(P[2*j + 2],  w2[3], sa);
            sa = f2fma(P[2*j + 4],  w2[1], sa);
            sa = f2fma(P[2*j + 6],  w2[1], sa);
            sa = f2fma(P[2*j + 8],  w2[3], sa);
            sa = f2fma(P[2*j + 10], w2[5], sa);
            u64 sb = f2mul(P[2*j + 1], w2[4]);
            sb = f2fma(P[2*j + 3],  w2[2], sb);
            sb = f2fma(P[2*j + 5],  w2[0], sb);
            sb = f2fma(P[2*j + 7],  w2[2], sb);
            sb = f2fma(P[2*j + 9],  w2[4], sb);
            h2[j] = f2add(sa, sb);
        }

        // ---- vertical taps: k=0..9 accumulate, k=10 overwrites recycled slot
#pragma unroll
        for (int k = 0; k < 10; ++k) {
            const u64 wv = w2[k <= 5 ? 5 - k : k - 5];
            const int s = (U + k) % 11;
            acc[s][0] = f2fma(h2[0], wv, acc[s][0]);
            acc[s][1] = f2fma(h2[1], wv, acc[s][1]);
            acc[s][2] = f2fma(h2[2], wv, acc[s][2]);
        }
        {
            const int s = (U + 10) % 11;
            acc[s][0] = f2mul(h2[0], w2[5]);
            acc[s][1] = f2mul(h2[1], w2[5]);
            acc[s][2] = f2mul(h2[2], w2[5]);
        }
    } else {
        const int s = (U + 10) % 11;
        acc[s][0] = 0ull; acc[s][1] = 0ull; acc[s][2] = 0ull;
    }

    if (EMIT) {
        float a0, a1, a2, a3, a4, a5;
        upk(acc[U][0], a0, a1);
        upk(acc[U][1], a2, a3);
        upk(acc[U][2], a4, a5);
        const float m01 = fmaxf(a0, a1);
        const float m23 = fmaxf(a2, a3);
        const float m45 = fmaxf(a4, a5);
        const float rowmax = fmaxf(fmaxf(m01, m23), m45);
        if (rowmax > bestv) {        // rare
            bestv = rowmax;
            int c = 5;
            if (a4 == rowmax) c = 4;
            if (a3 == rowmax) c = 3;
            if (a2 == rowmax) c = 2;
            if (a1 == rowmax) c = 1;
            if (a0 == rowmax) c = 0;
            bestlin = ebl + U * IW + c;
        }
    }

    cur[0] = nc0; cur[1] = nc1; cur[2] = nc2;
}

// One CTA (64 threads = 2 warps) per (b,k) image; warp w owns output rows
// [w*128, w*128+128), lane owns 6 columns (3 aligned pairs). Head (11
// guarded) + main (11x11 branch-free) + tail (6 guarded).
__global__ __launch_bounds__(64, 8)
void dark_decode_kernel(const float* __restrict__ hm,
                        float* __restrict__ out, int n_img)
{
    const int img  = blockIdx.x;
    const int warp = threadIdx.x >> 5;
    const int lane = threadIdx.x & 31;
    const float* __restrict__ ip = hm + (long long)img * (IH * IW);
    const int base = warp * 128;
    const int col0 = lane * 6;
    const bool l0  = (lane == 0);
    const bool l31 = (lane == 31);

    u64 w2[6];
#pragma unroll
    for (int k = 0; k < 6; ++k) w2[k] = pk(wt(k), wt(k));

    u64 acc[11][3];   // no init needed: every slot is overwritten before emit

    u64 cur[3];
    {   // row base-5 (warp0: OOB -> zeros)
        const int r0 = base - 5;
        if (r0 >= 0) {
            const u64* p = reinterpret_cast<const u64*>(ip + r0 * IW + col0);
            cur[0] = p[0]; cur[1] = p[1]; cur[2] = p[2];
        } else {
            cur[0] = 0ull; cur[1] = 0ull; cur[2] = 0ull;
        }
    }

    float bestv   = -3.4e38f;
    int   bestlin = 0;

    // ---- head: i = 0..10 (r = base-5+i), guarded; emit only at i=10 ----
    {
        const int eblh = (base - 10) * IW + col0;
#define HSTEP(U, EM) step<U, true, EM>(ip, ip, base - 5 + (U), col0, cur, acc, \
                                       w2, l0, l31, bestv, bestlin, eblh)
        HSTEP(0, false); HSTEP(1, false); HSTEP(2, false); HSTEP(3, false);
        HSTEP(4, false); HSTEP(5, false); HSTEP(6, false); HSTEP(7, false);
        HSTEP(8, false); HSTEP(9, false); HSTEP(10, true);
#undef HSTEP
    }

    // ---- main: i = 11..131, 11 blocks x 11 steps, branch-free ----
    {
        const float* rp = ip + (base + 7) * IW + col0;   // row r+1 at ib=0,U=0
        int ebl = (base + 1) * IW + col0;                // ro at ib=0,U=0
#define MSTEP(U) step<U, false, true>(rp, ip, 0, col0, cur, acc, w2, l0, l31, \
                                      bestv, bestlin, ebl)
        for (int ib = 0; ib < 11; ++ib) {
            MSTEP(0); MSTEP(1); MSTEP(2); MSTEP(3); MSTEP(4); MSTEP(5);
            MSTEP(6); MSTEP(7); MSTEP(8); MSTEP(9); MSTEP(10);
            rp  += 11 * IW;
            ebl += 11 * IW;
        }
#undef MSTEP
    }

    // ---- tail: i = 132..137 (U = 0..5), guarded, always emit ----
    {
        const int eblt = (base + 122) * IW + col0;
#define TSTEP(U) step<U, true, true>(ip, ip, base + 127 + (U), col0, cur, acc, \
                                     w2, l0, l31, bestv, bestlin, eblt)
        TSTEP(0); TSTEP(1); TSTEP(2); TSTEP(3); TSTEP(4); TSTEP(5);
#undef TSTEP
    }

    // intra-warp argmax reduce (larger value wins; tie -> smaller linear index)
#pragma unroll
    for (int off = 16; off >= 1; off >>= 1) {
        const float ov = __shfl_xor_sync(FULLMASK, bestv, off);
        const int   oi = __shfl_xor_sync(FULLMASK, bestlin, off);
        if (ov > bestv || (ov == bestv && oi < bestlin)) { bestv = ov; bestlin = oi; }
    }

    __shared__ float s_v[2];
    __shared__ int   s_i[2];
    if (lane == 0) { s_v[warp] = bestv; s_i[warp] = bestlin; }
    __syncthreads();
    if (warp != 0) return;

    float fv; int fl;
    {
        const float v0 = s_v[0], v1 = s_v[1];
        const int   i0 = s_i[0], i1 = s_i[1];
        if (v1 > v0 || (v1 == v0 && i1 < i0)) { fv = v1; fl = i1; }
        else                                  { fv = v0; fl = i0; }
    }
    const int py = fl / IW;
    const int px = fl - py * IW;

    float offx = 0.f, offy = 0.f;
    const bool bok = (px >= 1) && (px < IW - 1) && (py >= 1) && (py < IH - 1);
    if (bok) {
        // 39 hblur values: flat j in [0,39), rr = py-6 + j/3, cc = px-1 + j%3
        float h0 = 0.f, h1 = 0.f;
        {
            int j = lane;
            int rr = py - 6 + j / 3;
            int cc = px - 1 + (j - (j / 3) * 3);
            if (rr >= 0 && rr < IH) {
                const float* rp2 = ip + rr * IW;
                float s = 0.f;
#pragma unroll
                for (int d = -5; d <= 5; ++d) {
                    const int c = cc + d;
                    float v = 0.f;
                    if ((unsigned)c < (unsigned)IW) v = rp2[c];
                    s += v * wt(d < 0 ? -d : d);
                }
                h0 = s;
            }
            j = lane + 32;
            if (j < 39) {
                rr = py - 6 + j / 3;
                cc = px - 1 + (j - (j / 3) * 3);
                if (rr >= 0 && rr < IH) {
                    const float* rp2 = ip + rr * IW;
                    float s = 0.f;
#pragma unroll
                    for (int d = -5; d <= 5; ++d) {
                        const int c = cc + d;
                        float v = 0.f;
                        if ((unsigned)c < (unsigned)IW) v = rp2[c];
                        s += v * wt(d < 0 ? -d : d);
                    }
                    h1 = s;
                }
            }
        }
        // lanes 0..8: vertical blur -> patch entry p(a,b), a=lane/3, b=lane%3
        const int a = lane / 3;
        const int b = lane - a * 3;
        float p = 0.f;
#pragma unroll
        for (int t = 0; t < 11; ++t) {
            const int j = (a + t) * 3 + b;
            const float va = __shfl_sync(FULLMASK, h0, j & 31);
            const float vb = __shfl_sync(FULLMASK, h1, j & 31);
            const float hv = (j < 32) ? va : vb;
            p += hv * wt(t <= 5 ? 5 - t : t - 5);
        }
        const float p00 = __shfl_sync(FULLMASK, p, 0);
        const float p01 = __shfl_sync(FULLMASK, p, 1);
        const float p02 = __shfl_sync(FULLMASK, p, 2);
        const float p10 = __shfl_sync(FULLMASK, p, 3);
        const float p11 = __shfl_sync(FULLMASK, p, 4);
        const float p12 = __shfl_sync(FULLMASK, p, 5);
        const float p20 = __shfl_sync(FULLMASK, p, 6);
        const float p21 = __shfl_sync(FULLMASK, p, 7);
        const float p22 = __shfl_sync(FULLMASK, p, 8);

        const float dx  = (p12 - p10) * 0.5f;
        const float dy  = (p21 - p01) * 0.5f;
        const float dxx = p12 - 2.f * p11 + p10;
        const float dyy = p21 - 2.f * p11 + p01;
        const float dxy = (p22 - p20 - p02 + p00) * 0.25f;
        const float det = dxx * dyy - dxy * dxy;
        if (fabsf(det) >= 1e-6f && dxx < 0.f) {
            const float ox = -(dyy * dx - dxy * dy) / det;
            const float oy = -(dxx * dy - dxy * dx) / det;
            offx = fminf(fmaxf(ox, -0.5f), 0.5f);
            offy = fminf(fmaxf(oy, -0.5f), 0.5f);
        }
    }

    if (lane == 0) {
        const float xo = fminf(fmaxf((float)px + offx, 0.f), (float)(IW - 1));
        const float yo = fminf(fmaxf((float)py + offy, 0.f), (float)(IH - 1));
        out[2 * img + 0] = xo;                       // coords[...,0] = x
        out[2 * img + 1] = yo;                       // coords[...,1] = y
        out[(long long)2 * n_img + img] = fv;        // max_vals
    }
}

extern "C" void kernel_launch(void* const* d_in, const int* in_sizes, int n_in,
                              void* d_out, int out_size)
{
    const float* hm = (const float*)d_in[0];
    // d_in[1] is kernel_size (always 11 in this problem; taps are baked in)
    const int n_img = in_sizes[0] / (IH * IW);
    dark_decode_kernel<<<n_img, 64>>>(hm, (float*)d_out, n_img);
}

// round 15
// speedup vs baseline: 1.9279x; 1.0749x over previous
#include <cuda_runtime.h>

#define FULLMASK 0xffffffffu
#define IH 256
#define IW 192

typedef unsigned long long u64;

// Gaussian taps for kernel_size=11, sigma=10/6, normalized. Indexed by |d|.
static __device__ __forceinline__ float wt(int k) {
    const float t[6] = {0.23955940f, 0.20009682f, 0.11660614f,
                        0.04740849f, 0.01344761f, 0.00266126f};
    return t[k];
}

static __device__ __forceinline__ u64 pk(float lo, float hi) {
    u64 r; asm("mov.b64 %0, {%1, %2};" : "=l"(r) : "f"(lo), "f"(hi)); return r;
}
static __device__ __forceinline__ void upk(u64 v, float& lo, float& hi) {
    asm("mov.b64 {%0, %1}, %2;" : "=f"(lo), "=f"(hi) : "l"(v));
}
static __device__ __forceinline__ float f2lo(u64 v) { float a, b; upk(v, a, b); return a; }
static __device__ __forceinline__ float f2hi(u64 v) { float a, b; upk(v, a, b); return b; }
static __device__ __forceinline__ u64 f2mul(u64 a, u64 b) {
    u64 d; asm("mul.rn.f32x2 %0, %1, %2;" : "=l"(d) : "l"(a), "l"(b)); return d;
}
static __device__ __forceinline__ u64 f2fma(u64 a, u64 b, u64 c) {
    u64 d; asm("fma.rn.f32x2 %0, %1, %2, %3;" : "=l"(d) : "l"(a), "l"(b), "l"(c)); return d;
}
static __device__ __forceinline__ u64 f2add(u64 a, u64 b) {
    u64 d; asm("add.rn.f32x2 %0, %1, %2;" : "=l"(d) : "l"(a), "l"(b)); return d;
}

// One step, VERTICAL-FIRST formulation:
//  - every step: accumulate RAW input row r into the 11-slot rotating vblur
//    accumulator (33 packed FMAs), prefetch row r+1.
//  - EMIT steps only: slot U now holds the fully vblurred output row;
//    do the horizontal blur (halos via pair shuffles + symmetric pre-adds)
//    and fold the row max into the running argmax.
// This moves the hblur+shuffle+cross block from all 138 steps to the 128
// emit steps, and symmetric regrouping cuts hblur 12->11 ops per pair.
//  U      : static slot phase (i mod 11)
//  GUARD  : head/tail mode — runtime row/load bounds checks (warp-uniform)
template<int U, bool GUARD, bool EMIT>
static __device__ __forceinline__ void step(
    const float* __restrict__ rp,   // main-mode load base: row of U=0 load
    const float* __restrict__ ip,   // image base (GUARD-mode addressing)
    int r, int col0,
    u64 (&cur)[3], u64 (&acc)[11][3], const u64 (&w2)[6],
    bool l0, bool l31, float& bestv, int& bestlin, int ebl)
{
    // ---- load row r+1 (3 aligned pairs) ----
    u64 nc0 = 0ull, nc1 = 0ull, nc2 = 0ull;
    bool loadok = true, rowok = true;
    if (GUARD) {
        loadok = ((unsigned)(r + 1) < (unsigned)IH);
        rowok  = ((unsigned)r       < (unsigned)IH);
    }
    if (loadok) {
        const u64* p = reinterpret_cast<const u64*>(
            GUARD ? (ip + (r + 1) * IW + col0) : (rp + U * IW));
        nc0 = p[0]; nc1 = p[1]; nc2 = p[2];
    }

    // ---- vertical blur accumulation on RAW row r ----
    if (rowok) {
#pragma unroll
        for (int k = 0; k < 10; ++k) {
            const u64 wv = w2[k <= 5 ? 5 - k : k - 5];
            const int s = (U + k) % 11;
            acc[s][0] = f2fma(cur[0], wv, acc[s][0]);
            acc[s][1] = f2fma(cur[1], wv, acc[s][1]);
            acc[s][2] = f2fma(cur[2], wv, acc[s][2]);
        }
        {
            const int s = (U + 10) % 11;
            acc[s][0] = f2mul(cur[0], w2[5]);
            acc[s][1] = f2mul(cur[1], w2[5]);
            acc[s][2] = f2mul(cur[2], w2[5]);
        }
    } else {
        const int s = (U + 10) % 11;
        acc[s][0] = 0ull; acc[s][1] = 0ull; acc[s][2] = 0ull;
    }

    if (EMIT) {
        // slot U = vblurred output row (own 6 cols in 3 aligned pairs)
        const u64 v0 = acc[U][0], v1 = acc[U][1], v2 = acc[U][2];

        // pair halos via u64 shuffles (arrive pre-packed)
        u64 P1  = __shfl_up_sync(FULLMASK, v1, 1);     // (c0-4, c0-3)
        u64 P3  = __shfl_up_sync(FULLMASK, v2, 1);     // (c0-2, c0-1)
        u64 P11 = __shfl_down_sync(FULLMASK, v0, 1);   // (c0+6, c0+7)
        u64 P13 = __shfl_down_sync(FULLMASK, v1, 1);   // (c0+8, c0+9)
        float e0  = __shfl_up_sync(FULLMASK, f2hi(v0), 1);   // c0-5
        float e15 = __shfl_down_sync(FULLMASK, f2lo(v2), 1); // c0+10
        if (l0)  { P1 = 0ull; P3 = 0ull; e0 = 0.f; }
        if (l31) { P11 = 0ull; P13 = 0ull; e15 = 0.f; }

        // full pair set; 7 aligned (free), 8 crosses (2 MOV each)
        u64 P[15];
        P[0]  = pk(e0, f2lo(P1));
        P[1]  = P1;
        P[2]  = pk(f2hi(P1), f2lo(P3));
        P[3]  = P3;
        P[4]  = pk(f2hi(P3), f2lo(v0));
        P[5]  = v0;
        P[6]  = pk(f2hi(v0), f2lo(v1));
        P[7]  = v1;
        P[8]  = pk(f2hi(v1), f2lo(v2));
        P[9]  = v2;
        P[10] = pk(f2hi(v2), f2lo(P11));
        P[11] = P11;
        P[12] = pk(f2hi(P11), f2lo(P13));
        P[13] = P13;
        P[14] = pk(f2hi(P13), e15);

        // horizontal blur, symmetric pre-add form:
        // h = w5*(P[d0]+P[d10]) + w4*(P[d1]+P[d9]) + ... + w0*P[d5]
        u64 h2[3];
#pragma unroll
        for (int j = 0; j < 3; ++j) {
            const u64 t5 = f2add(P[2*j + 0], P[2*j + 10]);
            const u64 t4 = f2add(P[2*j + 1], P[2*j + 9]);
            const u64 t3 = f2add(P[2*j + 2], P[2*j + 8]);
            const u64 t2 = f2add(P[2*j + 3], P[2*j + 7]);
            const u64 t1 = f2add(P[2*j + 4], P[2*j + 6]);
            u64 s = f2mul(t5, w2[5]);
            s = f2fma(t4, w2[4], s);
            s = f2fma(t3, w2[3], s);
            s = f2fma(t2, w2[2], s);
            s = f2fma(t1, w2[1], s);
            s = f2fma(P[2*j + 5], w2[0], s);
            h2[j] = s;
        }

        float a0, a1, a2, a3, a4, a5;
        upk(h2[0], a0, a1);
        upk(h2[1], a2, a3);
        upk(h2[2], a4, a5);
        const float m01 = fmaxf(a0, a1);
        const float m23 = fmaxf(a2, a3);
        const float m45 = fmaxf(a4, a5);
        const float rowmax = fmaxf(fmaxf(m01, m23), m45);
        if (rowmax > bestv) {        // rare
            bestv = rowmax;
            int c = 5;
            if (a4 == rowmax) c = 4;
            if (a3 == rowmax) c = 3;
            if (a2 == rowmax) c = 2;
            if (a1 == rowmax) c = 1;
            if (a0 == rowmax) c = 0;
            bestlin = ebl + U * IW + c;
        }
    }

    cur[0] = nc0; cur[1] = nc1; cur[2] = nc2;
}

// One CTA (64 threads = 2 warps) per (b,k) image; warp w owns output rows
// [w*128, w*128+128), lane owns 6 columns (3 aligned pairs). Head (11
// guarded) + main (11x11 branch-free) + tail (6 guarded).
__global__ __launch_bounds__(64, 8)
void dark_decode_kernel(const float* __restrict__ hm,
                        float* __restrict__ out, int n_img)
{
    const int img  = blockIdx.x;
    const int warp = threadIdx.x >> 5;
    const int lane = threadIdx.x & 31;
    const float* __restrict__ ip = hm + (long long)img * (IH * IW);
    const int base = warp * 128;
    const int col0 = lane * 6;
    const bool l0  = (lane == 0);
    const bool l31 = (lane == 31);

    u64 w2[6];
#pragma unroll
    for (int k = 0; k < 6; ++k) w2[k] = pk(wt(k), wt(k));

    u64 acc[11][3];   // no init needed: every slot is overwritten before emit

    u64 cur[3];
    {   // row base-5 (warp0: OOB -> zeros)
        const int r0 = base - 5;
        if (r0 >= 0) {
            const u64* p = reinterpret_cast<const u64*>(ip + r0 * IW + col0);
            cur[0] = p[0]; cur[1] = p[1]; cur[2] = p[2];
        } else {
            cur[0] = 0ull; cur[1] = 0ull; cur[2] = 0ull;
        }
    }

    float bestv   = -3.4e38f;
    int   bestlin = 0;

    // ---- head: i = 0..10 (r = base-5+i), guarded; emit only at i=10 ----
    {
        const int eblh = (base - 10) * IW + col0;
#define HSTEP(U, EM) step<U, true, EM>(ip, ip, base - 5 + (U), col0, cur, acc, \
                                       w2, l0, l31, bestv, bestlin, eblh)
        HSTEP(0, false); HSTEP(1, false); HSTEP(2, false); HSTEP(3, false);
        HSTEP(4, false); HSTEP(5, false); HSTEP(6, false); HSTEP(7, false);
        HSTEP(8, false); HSTEP(9, false); HSTEP(10, true);
#undef HSTEP
    }

    // ---- main: i = 11..131, 11 blocks x 11 steps, branch-free ----
    {
        const float* rp = ip + (base + 7) * IW + col0;   // row r+1 at ib=0,U=0
        int ebl = (base + 1) * IW + col0;                // ro at ib=0,U=0
#define MSTEP(U) step<U, false, true>(rp, ip, 0, col0, cur, acc, w2, l0, l31, \
                                      bestv, bestlin, ebl)
        for (int ib = 0; ib < 11; ++ib) {
            MSTEP(0); MSTEP(1); MSTEP(2); MSTEP(3); MSTEP(4); MSTEP(5);
            MSTEP(6); MSTEP(7); MSTEP(8); MSTEP(9); MSTEP(10);
            rp  += 11 * IW;
            ebl += 11 * IW;
        }
#undef MSTEP
    }

    // ---- tail: i = 132..137 (U = 0..5), guarded, always emit ----
    {
        const int eblt = (base + 122) * IW + col0;
#define TSTEP(U) step<U, true, true>(ip, ip, base + 127 + (U), col0, cur, acc, \
                                     w2, l0, l31, bestv, bestlin, eblt)
        TSTEP(0); TSTEP(1); TSTEP(2); TSTEP(3); TSTEP(4); TSTEP(5);
#undef TSTEP
    }

    // intra-warp argmax reduce (larger value wins; tie -> smaller linear index)
#pragma unroll
    for (int off = 16; off >= 1; off >>= 1) {
        const float ov = __shfl_xor_sync(FULLMASK, bestv, off);
        const int   oi = __shfl_xor_sync(FULLMASK, bestlin, off);
        if (ov > bestv || (ov == bestv && oi < bestlin)) { bestv = ov; bestlin = oi; }
    }

    __shared__ float s_v[2];
    __shared__ int   s_i[2];
    if (lane == 0) { s_v[warp] = bestv; s_i[warp] = bestlin; }
    __syncthreads();
    if (warp != 0) return;

    float fv; int fl;
    {
        const float v0 = s_v[0], v1 = s_v[1];
        const int   i0 = s_i[0], i1 = s_i[1];
        if (v1 > v0 || (v1 == v0 && i1 < i0)) { fv = v1; fl = i1; }
        else                                  { fv = v0; fl = i0; }
    }
    const int py = fl / IW;
    const int px = fl - py * IW;

    float offx = 0.f, offy = 0.f;
    const bool bok = (px >= 1) && (px < IW - 1) && (py >= 1) && (py < IH - 1);
    if (bok) {
        // 39 hblur values: flat j in [0,39), rr = py-6 + j/3, cc = px-1 + j%3
        float h0 = 0.f, h1 = 0.f;
        {
            int j = lane;
            int rr = py - 6 + j / 3;
            int cc = px - 1 + (j - (j / 3) * 3);
            if (rr >= 0 && rr < IH) {
                const float* rp2 = ip + rr * IW;
                float s = 0.f;
#pragma unroll
                for (int d = -5; d <= 5; ++d) {
                    const int c = cc + d;
                    float v = 0.f;
                    if ((unsigned)c < (unsigned)IW) v = rp2[c];
                    s += v * wt(d < 0 ? -d : d);
                }
                h0 = s;
            }
            j = lane + 32;
            if (j < 39) {
                rr = py - 6 + j / 3;
                cc = px - 1 + (j - (j / 3) * 3);
                if (rr >= 0 && rr < IH) {
                    const float* rp2 = ip + rr * IW;
                    float s = 0.f;
#pragma unroll
                    for (int d = -5; d <= 5; ++d) {
                        const int c = cc + d;
                        float v = 0.f;
                        if ((unsigned)c < (unsigned)IW) v = rp2[c];
                        s += v * wt(d < 0 ? -d : d);
                    }
                    h1 = s;
                }
            }
        }
        // lanes 0..8: vertical blur -> patch entry p(a,b), a=lane/3, b=lane%3
        const int a = lane / 3;
        const int b = lane - a * 3;
        float p = 0.f;
#pragma unroll
        for (int t = 0; t < 11; ++t) {
            const int j = (a + t) * 3 + b;
            const float va = __shfl_sync(FULLMASK, h0, j & 31);
            const float vb = __shfl_sync(FULLMASK, h1, j & 31);
            const float hv = (j < 32) ? va : vb;
            p += hv * wt(t <= 5 ? 5 - t : t - 5);
        }
        const float p00 = __shfl_sync(FULLMASK, p, 0);
        const float p01 = __shfl_sync(FULLMASK, p, 1);
        const float p02 = __shfl_sync(FULLMASK, p, 2);
        const float p10 = __shfl_sync(FULLMASK, p, 3);
        const float p11 = __shfl_sync(FULLMASK, p, 4);
        const float p12 = __shfl_sync(FULLMASK, p, 5);
        const float p20 = __shfl_sync(FULLMASK, p, 6);
        const float p21 = __shfl_sync(FULLMASK, p, 7);
        const float p22 = __shfl_sync(FULLMASK, p, 8);

        const float dx  = (p12 - p10) * 0.5f;
        const float dy  = (p21 - p01) * 0.5f;
        const float dxx = p12 - 2.f * p11 + p10;
        const float dyy = p21 - 2.f * p11 + p01;
        const float dxy = (p22 - p20 - p02 + p00) * 0.25f;
        const float det = dxx * dyy - dxy * dxy;
        if (fabsf(det) >= 1e-6f && dxx < 0.f) {
            const float ox = -(dyy * dx - dxy * dy) / det;
            const float oy = -(dxx * dy - dxy * dx) / det;
            offx = fminf(fmaxf(ox, -0.5f), 0.5f);
            offy = fminf(fmaxf(oy, -0.5f), 0.5f);
        }
    }

    if (lane == 0) {
        const float xo = fminf(fmaxf((float)px + offx, 0.f), (float)(IW - 1));
        const float yo = fminf(fmaxf((float)py + offy, 0.f), (float)(IH - 1));
        out[2 * img + 0] = xo;                       // coords[...,0] = x
        out[2 * img + 1] = yo;                       // coords[...,1] = y
        out[(long long)2 * n_img + img] = fv;        // max_vals
    }
}

extern "C" void kernel_launch(void* const* d_in, const int* in_sizes, int n_in,
                              void* d_out, int out_size)
{
    const float* hm = (const float*)d_in[0];
    // d_in[1] is kernel_size (always 11 in this problem; taps are baked in)
    const int n_img = in_sizes[0] / (IH * IW);
    dark_decode_kernel<<<n_img, 64>>>(hm, (float*)d_out, n_img);
}

// round 16
// speedup vs baseline: 2.0868x; 1.0824x over previous
#include <cuda_runtime.h>

#define FULLMASK 0xffffffffu
#define IH 256
#define IW 192

typedef unsigned long long u64;

// Gaussian taps for kernel_size=11, sigma=10/6, normalized. Indexed by |d|.
static __device__ __forceinline__ float wt(int k) {
    const float t[6] = {0.23955940f, 0.20009682f, 0.11660614f,
                        0.04740849f, 0.01344761f, 0.00266126f};
    return t[k];
}

static __device__ __forceinline__ u64 pk(float lo, float hi) {
    u64 r; asm("mov.b64 %0, {%1, %2};" : "=l"(r) : "f"(lo), "f"(hi)); return r;
}
static __device__ __forceinline__ void upk(u64 v, float& lo, float& hi) {
    asm("mov.b64 {%0, %1}, %2;" : "=f"(lo), "=f"(hi) : "l"(v));
}
static __device__ __forceinline__ float f2lo(u64 v) { float a, b; upk(v, a, b); return a; }
static __device__ __forceinline__ float f2hi(u64 v) { float a, b; upk(v, a, b); return b; }
static __device__ __forceinline__ u64 f2mul(u64 a, u64 b) {
    u64 d; asm("mul.rn.f32x2 %0, %1, %2;" : "=l"(d) : "l"(a), "l"(b)); return d;
}
static __device__ __forceinline__ u64 f2fma(u64 a, u64 b, u64 c) {
    u64 d; asm("fma.rn.f32x2 %0, %1, %2, %3;" : "=l"(d) : "l"(a), "l"(b), "l"(c)); return d;
}
static __device__ __forceinline__ u64 f2add(u64 a, u64 b) {
    u64 d; asm("add.rn.f32x2 %0, %1, %2;" : "=l"(d) : "l"(a), "l"(b)); return d;
}

// One step, VERTICAL-FIRST formulation:
//  - every step: accumulate RAW input row r into the 11-slot rotating vblur
//    accumulator (33 packed FMAs), prefetch row r+1.
//  - EMIT steps only: slot U holds the fully vblurred output row; horizontal
//    blur with symmetric pre-adds. Cross-parity sums are computed as SCALAR
//    add.rn pairs written into fresh aligned destination pairs (no cross-pair
//    MOV builds); aligned-parity sums stay packed. Lanewise bit-identical to
//    the all-packed form.
//  U      : static slot phase (i mod 11)
//  GUARD  : head/tail mode — runtime row/load bounds checks (warp-uniform)
template<int U, bool GUARD, bool EMIT>
static __device__ __forceinline__ void step(
    const float* __restrict__ rp,   // main-mode load base: row of U=0 load
    const float* __restrict__ ip,   // image base (GUARD-mode addressing)
    int r, int col0,
    u64 (&cur)[3], u64 (&acc)[11][3], const u64 (&w2)[6],
    bool l0, bool l31, float& bestv, int& bestlin, int ebl)
{
    // ---- load row r+1 (3 aligned pairs) ----
    u64 nc0 = 0ull, nc1 = 0ull, nc2 = 0ull;
    bool loadok = true, rowok = true;
    if (GUARD) {
        loadok = ((unsigned)(r + 1) < (unsigned)IH);
        rowok  = ((unsigned)r       < (unsigned)IH);
    }
    if (loadok) {
        const u64* p = reinterpret_cast<const u64*>(
            GUARD ? (ip + (r + 1) * IW + col0) : (rp + U * IW));
        nc0 = p[0]; nc1 = p[1]; nc2 = p[2];
    }

    // ---- vertical blur accumulation on RAW row r ----
    if (rowok) {
#pragma unroll
        for (int k = 0; k < 10; ++k) {
            const u64 wv = w2[k <= 5 ? 5 - k : k - 5];
            const int s = (U + k) % 11;
            acc[s][0] = f2fma(cur[0], wv, acc[s][0]);
            acc[s][1] = f2fma(cur[1], wv, acc[s][1]);
            acc[s][2] = f2fma(cur[2], wv, acc[s][2]);
        }
        {
            const int s = (U + 10) % 11;
            acc[s][0] = f2mul(cur[0], w2[5]);
            acc[s][1] = f2mul(cur[1], w2[5]);
            acc[s][2] = f2mul(cur[2], w2[5]);
        }
    } else {
        const int s = (U + 10) % 11;
        acc[s][0] = 0ull; acc[s][1] = 0ull; acc[s][2] = 0ull;
    }

    if (EMIT) {
        // slot U = vblurred output row (own 6 cols in 3 aligned pairs)
        const u64 v0 = acc[U][0], v1 = acc[U][1], v2 = acc[U][2];

        // pair halos via u64 shuffles (arrive pre-packed)
        u64 P1  = __shfl_up_sync(FULLMASK, v1, 1);     // (c0-4, c0-3)
        u64 P3  = __shfl_up_sync(FULLMASK, v2, 1);     // (c0-2, c0-1)
        u64 P11 = __shfl_down_sync(FULLMASK, v0, 1);   // (c0+6, c0+7)
        u64 P13 = __shfl_down_sync(FULLMASK, v1, 1);   // (c0+8, c0+9)
        float e0  = __shfl_up_sync(FULLMASK, f2hi(v0), 1);   // c0-5
        float e15 = __shfl_down_sync(FULLMASK, f2lo(v2), 1); // c0+10
        if (l0)  { P1 = 0ull; P3 = 0ull; e0 = 0.f; }
        if (l31) { P11 = 0ull; P13 = 0ull; e15 = 0.f; }

        // extended row e[0..15] as scalar refs (register halves, free)
        const float e1 = f2lo(P1),  e2 = f2hi(P1);
        const float e3 = f2lo(P3),  e4 = f2hi(P3);
        const float e5 = f2lo(v0),  e6 = f2hi(v0);
        const float e7 = f2lo(v1),  e8 = f2hi(v1);
        const float e9 = f2lo(v2),  e10 = f2hi(v2);
        const float e11 = f2lo(P11), e12 = f2hi(P11);
        const float e13 = f2lo(P13), e14 = f2hi(P13);
        const float e[16] = {e0, e1, e2, e3, e4, e5, e6, e7,
                             e8, e9, e10, e11, e12, e13, e14, e15};
        // aligned pairs indexed as P[2m+1]
        const u64 PA[7] = {P1, P3, v0, v1, v2, P11, P13};  // P[1],P[3],..,P[13]

        // horizontal blur, symmetric pre-add form; cross-parity sums built
        // from scalar adds into fresh aligned pairs (pack elided by ptxas).
        u64 h2[3];
#pragma unroll
        for (int j = 0; j < 3; ++j) {
            const u64 t5 = pk(e[2*j + 0] + e[2*j + 10], e[2*j + 1] + e[2*j + 11]);
            const u64 t3 = pk(e[2*j + 2] + e[2*j + 8],  e[2*j + 3] + e[2*j + 9]);
            const u64 t1 = pk(e[2*j + 4] + e[2*j + 6],  e[2*j + 5] + e[2*j + 7]);
            const u64 t4 = f2add(PA[j], PA[j + 4]);        // P[2j+1]+P[2j+9]
            const u64 t2 = f2add(PA[j + 1], PA[j + 3]);    // P[2j+3]+P[2j+7]
            u64 s = f2mul(t5, w2[5]);
            s = f2fma(t4, w2[4], s);
            s = f2fma(t3, w2[3], s);
            s = f2fma(t2, w2[2], s);
            s = f2fma(t1, w2[1], s);
            s = f2fma(PA[j + 2], w2[0], s);                // center P[2j+5]
            h2[j] = s;
        }

        float a0, a1, a2, a3, a4, a5;
        upk(h2[0], a0, a1);
        upk(h2[1], a2, a3);
        upk(h2[2], a4, a5);
        const float m01 = fmaxf(a0, a1);
        const float m23 = fmaxf(a2, a3);
        const float m45 = fmaxf(a4, a5);
        const float rowmax = fmaxf(fmaxf(m01, m23), m45);
        if (rowmax > bestv) {        // rare
            bestv = rowmax;
            int c = 5;
            if (a4 == rowmax) c = 4;
            if (a3 == rowmax) c = 3;
            if (a2 == rowmax) c = 2;
            if (a1 == rowmax) c = 1;
            if (a0 == rowmax) c = 0;
            bestlin = ebl + U * IW + c;
        }
    }

    cur[0] = nc0; cur[1] = nc1; cur[2] = nc2;
}

// One CTA (64 threads = 2 warps) per (b,k) image; warp w owns output rows
// [w*128, w*128+128), lane owns 6 columns (3 aligned pairs). Head (11
// guarded) + main (11x11 branch-free) + tail (6 guarded).
__global__ __launch_bounds__(64, 8)
void dark_decode_kernel(const float* __restrict__ hm,
                        float* __restrict__ out, int n_img)
{
    const int img  = blockIdx.x;
    const int warp = threadIdx.x >> 5;
    const int lane = threadIdx.x & 31;
    const float* __restrict__ ip = hm + (long long)img * (IH * IW);
    const int base = warp * 128;
    const int col0 = lane * 6;
    const bool l0  = (lane == 0);
    const bool l31 = (lane == 31);

    u64 w2[6];
#pragma unroll
    for (int k = 0; k < 6; ++k) w2[k] = pk(wt(k), wt(k));

    u64 acc[11][3];   // no init needed: every slot is overwritten before emit

    u64 cur[3];
    {   // row base-5 (warp0: OOB -> zeros)
        const int r0 = base - 5;
        if (r0 >= 0) {
            const u64* p = reinterpret_cast<const u64*>(ip + r0 * IW + col0);
            cur[0] = p[0]; cur[1] = p[1]; cur[2] = p[2];
        } else {
            cur[0] = 0ull; cur[1] = 0ull; cur[2] = 0ull;
        }
    }

    float bestv   = -3.4e38f;
    int   bestlin = 0;

    // ---- head: i = 0..10 (r = base-5+i), guarded; emit only at i=10 ----
    {
        const int eblh = (base - 10) * IW + col0;
#define HSTEP(U, EM) step<U, true, EM>(ip, ip, base - 5 + (U), col0, cur, acc, \
                                       w2, l0, l31, bestv, bestlin, eblh)
        HSTEP(0, false); HSTEP(1, false); HSTEP(2, false); HSTEP(3, false);
        HSTEP(4, false); HSTEP(5, false); HSTEP(6, false); HSTEP(7, false);
        HSTEP(8, false); HSTEP(9, false); HSTEP(10, true);
#undef HSTEP
    }

    // ---- main: i = 11..131, 11 blocks x 11 steps, branch-free ----
    {
        const float* rp = ip + (base + 7) * IW + col0;   // row r+1 at ib=0,U=0
        int ebl = (base + 1) * IW + col0;                // ro at ib=0,U=0
#define MSTEP(U) step<U, false, true>(rp, ip, 0, col0, cur, acc, w2, l0, l31, \
                                      bestv, bestlin, ebl)
        for (int ib = 0; ib < 11; ++ib) {
            MSTEP(0); MSTEP(1); MSTEP(2); MSTEP(3); MSTEP(4); MSTEP(5);
            MSTEP(6); MSTEP(7); MSTEP(8); MSTEP(9); MSTEP(10);
            rp  += 11 * IW;
            ebl += 11 * IW;
        }
#undef MSTEP
    }

    // ---- tail: i = 132..137 (U = 0..5), guarded, always emit ----
    {
        const int eblt = (base + 122) * IW + col0;
#define TSTEP(U) step<U, true, true>(ip, ip, base + 127 + (U), col0, cur, acc, \
                                     w2, l0, l31, bestv, bestlin, eblt)
        TSTEP(0); TSTEP(1); TSTEP(2); TSTEP(3); TSTEP(4); TSTEP(5);
#undef TSTEP
    }

    // intra-warp argmax reduce (larger value wins; tie -> smaller linear index)
#pragma unroll
    for (int off = 16; off >= 1; off >>= 1) {
        const float ov = __shfl_xor_sync(FULLMASK, bestv, off);
        const int   oi = __shfl_xor_sync(FULLMASK, bestlin, off);
        if (ov > bestv || (ov == bestv && oi < bestlin)) { bestv = ov; bestlin = oi; }
    }

    __shared__ float s_v[2];
    __shared__ int   s_i[2];
    if (lane == 0) { s_v[warp] = bestv; s_i[warp] = bestlin; }
    __syncthreads();
    if (warp != 0) return;

    float fv; int fl;
    {
        const float v0 = s_v[0], v1 = s_v[1];
        const int   i0 = s_i[0], i1 = s_i[1];
        if (v1 > v0 || (v1 == v0 && i1 < i0)) { fv = v1; fl = i1; }
        else                                  { fv = v0; fl = i0; }
    }
    const int py = fl / IW;
    const int px = fl - py * IW;

    float offx = 0.f, offy = 0.f;
    const bool bok = (px >= 1) && (px < IW - 1) && (py >= 1) && (py < IH - 1);
    if (bok) {
        // 39 hblur values: flat j in [0,39), rr = py-6 + j/3, cc = px-1 + j%3
        float h0 = 0.f, h1 = 0.f;
        {
            int j = lane;
            int rr = py - 6 + j / 3;
            int cc = px - 1 + (j - (j / 3) * 3);
            if (rr >= 0 && rr < IH) {
                const float* rp2 = ip + rr * IW;
                float s = 0.f;
#pragma unroll
                for (int d = -5; d <= 5; ++d) {
                    const int c = cc + d;
                    float v = 0.f;
                    if ((unsigned)c < (unsigned)IW) v = rp2[c];
                    s += v * wt(d < 0 ? -d : d);
                }
                h0 = s;
            }
            j = lane + 32;
            if (j < 39) {
                rr = py - 6 + j / 3;
                cc = px - 1 + (j - (j / 3) * 3);
                if (rr >= 0 && rr < IH) {
                    const float* rp2 = ip + rr * IW;
                    float s = 0.f;
#pragma unroll
                    for (int d = -5; d <= 5; ++d) {
                        const int c = cc + d;
                        float v = 0.f;
                        if ((unsigned)c < (unsigned)IW) v = rp2[c];
                        s += v * wt(d < 0 ? -d : d);
                    }
                    h1 = s;
                }
            }
        }
        // lanes 0..8: vertical blur -> patch entry p(a,b), a=lane/3, b=lane%3
        const int a = lane / 3;
        const int b = lane - a * 3;
        float p = 0.f;
#pragma unroll
        for (int t = 0; t < 11; ++t) {
            const int j = (a + t) * 3 + b;
            const float va = __shfl_sync(FULLMASK, h0, j & 31);
            const float vb = __shfl_sync(FULLMASK, h1, j & 31);
            const float hv = (j < 32) ? va : vb;
            p += hv * wt(t <= 5 ? 5 - t : t - 5);
        }
        const float p00 = __shfl_sync(FULLMASK, p, 0);
        const float p01 = __shfl_sync(FULLMASK, p, 1);
        const float p02 = __shfl_sync(FULLMASK, p, 2);
        const float p10 = __shfl_sync(FULLMASK, p, 3);
        const float p11 = __shfl_sync(FULLMASK, p, 4);
        const float p12 = __shfl_sync(FULLMASK, p, 5);
        const float p20 = __shfl_sync(FULLMASK, p, 6);
        const float p21 = __shfl_sync(FULLMASK, p, 7);
        const float p22 = __shfl_sync(FULLMASK, p, 8);

        const float dx  = (p12 - p10) * 0.5f;
        const float dy  = (p21 - p01) * 0.5f;
        const float dxx = p12 - 2.f * p11 + p10;
        const float dyy = p21 - 2.f * p11 + p01;
        const float dxy = (p22 - p20 - p02 + p00) * 0.25f;
        const float det = dxx * dyy - dxy * dxy;
        if (fabsf(det) >= 1e-6f && dxx < 0.f) {
            const float ox = -(dyy * dx - dxy * dy) / det;
            const float oy = -(dxx * dy - dxy * dx) / det;
            offx = fminf(fmaxf(ox, -0.5f), 0.5f);
            offy = fminf(fmaxf(oy, -0.5f), 0.5f);
        }
    }

    if (lane == 0) {
        const float xo = fminf(fmaxf((float)px + offx, 0.f), (float)(IW - 1));
        const float yo = fminf(fmaxf((float)py + offy, 0.f), (float)(IH - 1));
        out[2 * img + 0] = xo;                       // coords[...,0] = x
        out[2 * img + 1] = yo;                       // coords[...,1] = y
        out[(long long)2 * n_img + img] = fv;        // max_vals
    }
}

extern "C" void kernel_launch(void* const* d_in, const int* in_sizes, int n_in,
                              void* d_out, int out_size)
{
    const float* hm = (const float*)d_in[0];
    // d_in[1] is kernel_size (always 11 in this problem; taps are baked in)
    const int n_img = in_sizes[0] / (IH * IW);
    dark_decode_kernel<<<n_img, 64>>>(hm, (float*)d_out, n_img);
}